// round 15
// baseline (speedup 1.0000x reference)
#include <cuda_runtime.h>
#include <cuda_fp16.h>
#include <math.h>
#include <stdint.h>

// NeRF fused renderer, R9: two independent 256-thread warp-groups per CTA,
// each owning its own ray stream with named barriers -> prologue/epilogue of
// one group overlaps the other group's HMMA mainloop. Persistent grid=148.
// B (W2 fp16) + W1 table staged once per SM; A-table build is SMEM-only.

namespace {
constexpr float NEARV = 0.1f, FARV = 4.0f, EPSV = 1e-6f;
constexpr int AS = 264;                         // B row stride in halves
constexpr int OFF_B    = 0;                     // [256][AS] fp16 = 135168
constexpr int OFF_W1T  = 135168;                // float4[256]: w0,w1,w2,b1
constexpr int OFF_HDW  = OFF_W1T + 4096;        // float4[256]
constexpr int OFF_B2S  = OFF_HDW + 4096;        // float[256]
constexpr int OFF_ACBC = OFF_B2S + 1024;        // uint4[2][64]
constexpr int OFF_E    = OFF_ACBC + 2048;       // float[2][4]
constexpr int OFF_RED  = OFF_E + 32;            // [2][128][9][4] f32 = 36864
constexpr int OFF_CBUF = OFF_RED + 36864;       // float[2][4][128]
constexpr int SMEM_REQ = OFF_CBUF + 4096;       // 187424 B
}

__device__ __half g_W2h[256 * 256];             // fp16 W2 [k][j]

__global__ void prep_w2h(const float* __restrict__ W2) {
    int i = (blockIdx.x * 256 + threadIdx.x) * 4;
    float4 v = *(const float4*)(W2 + i);
    ((__half2*)g_W2h)[i / 2]     = __floats2half2_rn(v.x, v.y);
    ((__half2*)g_W2h)[i / 2 + 1] = __floats2half2_rn(v.z, v.w);
}

__device__ __forceinline__ void ldsm_x4_t(uint32_t* r, uint32_t a) {
    asm volatile("ldmatrix.sync.aligned.m8n8.x4.trans.shared.b16 {%0,%1,%2,%3}, [%4];"
                 : "=r"(r[0]), "=r"(r[1]), "=r"(r[2]), "=r"(r[3]) : "r"(a));
}
__device__ __forceinline__ void mma16816(float* c, const uint32_t* a,
                                         const uint32_t* b) {
    asm volatile(
        "mma.sync.aligned.m16n8k16.row.col.f32.f16.f16.f32 "
        "{%0,%1,%2,%3}, {%4,%5,%6,%7}, {%8,%9}, {%0,%1,%2,%3};"
        : "+f"(c[0]), "+f"(c[1]), "+f"(c[2]), "+f"(c[3])
        : "r"(a[0]), "r"(a[1]), "r"(a[2]), "r"(a[3]), "r"(b[0]), "r"(b[1]));
}
__device__ __forceinline__ void barg(int id) {
    asm volatile("bar.sync %0, 256;" :: "r"(id) : "memory");
}

__global__ __launch_bounds__(512, 1)
void nerf_mma6_kernel(const float* __restrict__ cam,
                      const float* __restrict__ rayv,
                      const float* __restrict__ W1,
                      const float* __restrict__ b1,
                      const float* __restrict__ b2,
                      const float* __restrict__ Wsig,
                      const float* __restrict__ bsig,
                      const float* __restrict__ Wrgb,
                      const float* __restrict__ brgb,
                      float* __restrict__ out,
                      int nrays)
{
    extern __shared__ char smem[];
    uint32_t smb;
    asm("{ .reg .u64 t; cvta.to.shared.u64 t, %1; cvt.u32.u64 %0, t; }"
        : "=r"(smb) : "l"(smem));

    const int tid = threadIdx.x;

    // ---- one-time staging (all 512 threads) ----
    {
        const uint4* src = (const uint4*)g_W2h;
        #pragma unroll
        for (int it = 0; it < 16; ++it) {
            int idx = tid + it * 512;
            int row = idx >> 5, c = idx & 31;
            *(uint4*)(smem + OFF_B + (row * AS + c * 8) * 2) = src[idx];
        }
    }
    if (tid < 256) {
        int k = tid;
        ((float4*)(smem + OFF_W1T))[k] =
            make_float4(W1[k], W1[256 + k], W1[512 + k], b1[k]);
        ((float4*)(smem + OFF_HDW))[k] =
            make_float4(Wsig[k], Wrgb[k*3+0], Wrgb[k*3+1], Wrgb[k*3+2]);
        ((float*)(smem + OFF_B2S))[k] = b2[k];
    }
    __syncthreads();

    // ---- group decomposition: g owns its own ray stream ----
    const int g = tid >> 8, gtid = tid & 255;
    const int wg = gtid >> 5, lane = gtid & 31;
    const int wm = wg & 3, wn_ = wg >> 2;
    const int q = lane & 3, rowq = lane >> 2;
    const int krow = lane & 15, bcol = (lane >> 4) * 8;
    const int barid = g + 1;

    __half2 zz[4];
    #pragma unroll
    for (int i = 0; i < 4; ++i) {
        int m = wm * 32 + (i >> 1) * 16 + rowq + (i & 1) * 8;   // p = m, 0..127
        float t = (float)m * (1.0f / 127.0f);
        zz[i] = __float2half2_rn(NEARV * (1.0f - t) + FARV * t);
    }
    const __half2 h2zero = __float2half2_rn(0.0f);
    const uint4* actab = (const uint4*)(smem + OFF_ACBC) + g * 64 + q;
    const float* b2s = (const float*)(smem + OFF_B2S);
    const float4* hdw = (const float4*)(smem + OFF_HDW);
    const float4* w1t = (const float4*)(smem + OFF_W1T);
    float* red = (float*)(smem + OFF_RED) + g * 4608;           // 128*9*4
    float* cbuf = (float*)(smem + OFF_CBUF) + g * 512;
    float* eg = (float*)(smem + OFF_E) + g * 4;
    const int slot = wn_ * 4 + q;

    for (int ray = blockIdx.x * 2 + g; ray < nrays; ray += 296) {
        // ---- per-ray prologue: A-gen table from SMEM W1 table ----
        if (gtid < 67) {
            float v0 = rayv[ray*3+0], v1 = rayv[ray*3+1], v2 = rayv[ray*3+2];
            float inv = rsqrtf(v0*v0 + v1*v1 + v2*v2);
            float dxr = v0*inv, dyr = v1*inv, dzr = v2*inv;
            if (gtid < 64) {
                int ks = gtid >> 2, qq = gtid & 3;
                int k0 = ks * 16 + qq * 2;
                float cc0 = cam[ray*3+0], cc1 = cam[ray*3+1], cc2 = cam[ray*3+2];
                float acf[4], bcf[4];
                #pragma unroll
                for (int u = 0; u < 4; ++u) {
                    int k = k0 + (u >> 1) * 8 + (u & 1);
                    float4 wv = w1t[k];
                    acf[u] = cc0*wv.x + cc1*wv.y + cc2*wv.z + wv.w;
                    bcf[u] = dxr*wv.x + dyr*wv.y + dzr*wv.z;
                }
                __half2 ac01 = __floats2half2_rn(acf[0], acf[1]);
                __half2 bc01 = __floats2half2_rn(bcf[0], bcf[1]);
                __half2 ac89 = __floats2half2_rn(acf[2], acf[3]);
                __half2 bc89 = __floats2half2_rn(bcf[2], bcf[3]);
                uint4 e;
                e.x = *(uint32_t*)&ac01; e.y = *(uint32_t*)&bc01;
                e.z = *(uint32_t*)&ac89; e.w = *(uint32_t*)&bc89;
                ((uint4*)(smem + OFF_ACBC))[g * 64 + gtid] = e;
            } else {
                int t = gtid - 64;     // 0..2
                eg[t] = brgb[t] - (dxr * Wrgb[(256+0)*3 + t] +
                                   dyr * Wrgb[(256+1)*3 + t] +
                                   dzr * Wrgb[(256+2)*3 + t]);
            }
        }
        barg(barid);

        // ---- mainloop: M=128 (this ray), N=256 in two passes ----
        float s[4][4];
        #pragma unroll
        for (int i = 0; i < 4; ++i)
            #pragma unroll
            for (int h = 0; h < 4; ++h) s[i][h] = 0.0f;

        #pragma unroll 1
        for (int pp = 0; pp < 2; ++pp) {
            const int n0 = pp * 128 + wn_ * 64;
            uint32_t baddr[4];
            #pragma unroll
            for (int nf2 = 0; nf2 < 4; ++nf2)
                baddr[nf2] = smb + OFF_B + (krow * AS + n0 + nf2 * 16 + bcol) * 2;

            float acc[2][8][4];
            #pragma unroll
            for (int mf = 0; mf < 2; ++mf)
                #pragma unroll
                for (int nf = 0; nf < 8; ++nf)
                    #pragma unroll
                    for (int c = 0; c < 4; ++c) acc[mf][nf][c] = 0.0f;

            #pragma unroll
            for (int ks = 0; ks < 16; ++ks) {
                uint4 e = actab[ks * 4];
                __half2 ac01 = *(__half2*)&e.x, bc01 = *(__half2*)&e.y;
                __half2 ac89 = *(__half2*)&e.z, bc89 = *(__half2*)&e.w;
                uint32_t a[2][4];
                #pragma unroll
                for (int mf = 0; mf < 2; ++mf) {
                    __half2 h0 = __hmax2(__hfma2(bc01, zz[mf*2],   ac01), h2zero);
                    __half2 h1 = __hmax2(__hfma2(bc01, zz[mf*2+1], ac01), h2zero);
                    __half2 h2 = __hmax2(__hfma2(bc89, zz[mf*2],   ac89), h2zero);
                    __half2 h3 = __hmax2(__hfma2(bc89, zz[mf*2+1], ac89), h2zero);
                    a[mf][0] = *(uint32_t*)&h0;
                    a[mf][1] = *(uint32_t*)&h1;
                    a[mf][2] = *(uint32_t*)&h2;
                    a[mf][3] = *(uint32_t*)&h3;
                }
                #pragma unroll
                for (int nf2 = 0; nf2 < 4; ++nf2) {
                    uint32_t b[4];
                    ldsm_x4_t(b, baddr[nf2] + ks * (16 * AS * 2));
                    #pragma unroll
                    for (int mf = 0; mf < 2; ++mf) {
                        mma16816(acc[mf][nf2*2],     a[mf], b);
                        mma16816(acc[mf][nf2*2 + 1], a[mf], b + 2);
                    }
                }
            }

            #pragma unroll
            for (int nf = 0; nf < 8; ++nf) {
                int j0 = n0 + nf * 8 + q * 2;
                float bb0 = b2s[j0], bb1 = b2s[j0 + 1];
                float4 w0v = hdw[j0], w1v = hdw[j0 + 1];
                #pragma unroll
                for (int mf = 0; mf < 2; ++mf) {
                    float h00 = fmaxf(acc[mf][nf][0] + bb0, 0.0f);
                    float h01 = fmaxf(acc[mf][nf][1] + bb1, 0.0f);
                    float h10 = fmaxf(acc[mf][nf][2] + bb0, 0.0f);
                    float h11 = fmaxf(acc[mf][nf][3] + bb1, 0.0f);
                    s[mf*2][0]   = fmaf(h00, w0v.x, fmaf(h01, w1v.x, s[mf*2][0]));
                    s[mf*2][1]   = fmaf(h00, w0v.y, fmaf(h01, w1v.y, s[mf*2][1]));
                    s[mf*2][2]   = fmaf(h00, w0v.z, fmaf(h01, w1v.z, s[mf*2][2]));
                    s[mf*2][3]   = fmaf(h00, w0v.w, fmaf(h01, w1v.w, s[mf*2][3]));
                    s[mf*2+1][0] = fmaf(h10, w0v.x, fmaf(h11, w1v.x, s[mf*2+1][0]));
                    s[mf*2+1][1] = fmaf(h10, w0v.y, fmaf(h11, w1v.y, s[mf*2+1][1]));
                    s[mf*2+1][2] = fmaf(h10, w0v.z, fmaf(h11, w1v.z, s[mf*2+1][2]));
                    s[mf*2+1][3] = fmaf(h10, w0v.w, fmaf(h11, w1v.w, s[mf*2+1][3]));
                }
            }
        }

        // ---- slot write + reduce (group-local) ----
        #pragma unroll
        for (int i = 0; i < 4; ++i) {
            int m = wm * 32 + (i >> 1) * 16 + rowq + (i & 1) * 8;
            *(float4*)(red + (m * 9 + slot) * 4) =
                make_float4(s[i][0], s[i][1], s[i][2], s[i][3]);
        }
        barg(barid);

        if (gtid < 128) {
            int p = gtid;
            float4 t0 = *(float4*)(red + (p * 9 + 0) * 4);
            #pragma unroll
            for (int sl = 1; sl < 8; ++sl) {
                float4 t = *(float4*)(red + (p * 9 + sl) * 4);
                t0.x += t.x; t0.y += t.y; t0.z += t.z; t0.w += t.w;
            }
            float sigma = fmaxf(t0.x + bsig[0], 0.0f);
            float ta = (float)p * (1.0f / 127.0f);
            float z0 = NEARV * (1.0f - ta) + FARV * ta;
            float tb = (float)(p + 1) * (1.0f / 127.0f);
            float z1 = NEARV * (1.0f - tb) + FARV * tb;
            float alpha = (p < 127) ? (1.0f - expf(-sigma * (z1 - z0))) : 1.0f;
            cbuf[p]       = alpha;
            cbuf[128 + p] = 1.0f / (1.0f + expf(-(t0.y + eg[0])));
            cbuf[256 + p] = 1.0f / (1.0f + expf(-(t0.z + eg[1])));
            cbuf[384 + p] = 1.0f / (1.0f + expf(-(t0.w + eg[2])));
        }
        barg(barid);

        // ---- warp-parallel composite (warp 0 of group) ----
        if (wg == 0) {
            int s0i = lane * 4;
            float a0 = cbuf[s0i], a1 = cbuf[s0i+1], a2 = cbuf[s0i+2], a3 = cbuf[s0i+3];
            float f0 = 1.0f - a0 + EPSV, f1 = 1.0f - a1 + EPSV;
            float f2 = 1.0f - a2 + EPSV, f3 = 1.0f - a3 + EPSV;
            float I = f0 * f1 * f2 * f3;
            #pragma unroll
            for (int d = 1; d < 32; d <<= 1) {
                float t = __shfl_up_sync(0xffffffffu, I, d);
                if (lane >= d) I *= t;
            }
            float E = __shfl_up_sync(0xffffffffu, I, 1);
            if (lane == 0) E = 1.0f;
            float T1 = E * f0, T2 = T1 * f1, T3 = T2 * f2;
            float w0 = a0 * E, w1 = a1 * T1, w2 = a2 * T2, w3 = a3 * T3;
            float o[3];
            #pragma unroll
            for (int ch = 0; ch < 3; ++ch) {
                const float* cc = cbuf + 128 * (ch + 1) + s0i;
                o[ch] = fmaf(w0, cc[0], fmaf(w1, cc[1],
                        fmaf(w2, cc[2], w3 * cc[3])));
                #pragma unroll
                for (int d = 16; d; d >>= 1)
                    o[ch] += __shfl_xor_sync(0xffffffffu, o[ch], d);
            }
            if (lane == 0) {
                out[ray*3 + 0] = o[0];
                out[ray*3 + 1] = o[1];
                out[ray*3 + 2] = o[2];
            }
        }
    }
}

extern "C" void kernel_launch(void* const* d_in, const int* in_sizes, int n_in,
                              void* d_out, int out_size)
{
    const float* cam  = (const float*)d_in[0];
    const float* rayv = (const float*)d_in[1];
    const float* W1   = (const float*)d_in[2];
    const float* b1   = (const float*)d_in[3];
    const float* W2   = (const float*)d_in[4];
    const float* b2   = (const float*)d_in[5];
    const float* Wsig = (const float*)d_in[6];
    const float* bsig = (const float*)d_in[7];
    const float* Wrgb = (const float*)d_in[8];
    const float* brgb = (const float*)d_in[9];
    float* out = (float*)d_out;

    const int nrays = in_sizes[0] / 3;     // 4096

    prep_w2h<<<64, 256>>>(W2);

    cudaFuncSetAttribute(nerf_mma6_kernel,
                         cudaFuncAttributeMaxDynamicSharedMemorySize, SMEM_REQ);
    nerf_mma6_kernel<<<148, 512, SMEM_REQ>>>(cam, rayv, W1, b1, b2,
                                             Wsig, bsig, Wrgb, brgb, out, nrays);
}

// round 16
// speedup vs baseline: 1.0092x; 1.0092x over previous
#include <cuda_runtime.h>
#include <cuda_fp16.h>
#include <math.h>
#include <stdint.h>

// NeRF fused renderer, R9: two independent 256-thread warp-groups per CTA,
// each owning its own ray stream with named barriers -> prologue/epilogue of
// one group overlaps the other group's HMMA mainloop. Persistent grid=148.
// B (W2 fp16) + W1 table staged once per SM; A-table build is SMEM-only.

namespace {
constexpr float NEARV = 0.1f, FARV = 4.0f, EPSV = 1e-6f;
constexpr int AS = 264;                         // B row stride in halves
constexpr int OFF_B    = 0;                     // [256][AS] fp16 = 135168
constexpr int OFF_W1T  = 135168;                // float4[256]: w0,w1,w2,b1
constexpr int OFF_HDW  = OFF_W1T + 4096;        // float4[256]
constexpr int OFF_B2S  = OFF_HDW + 4096;        // float[256]
constexpr int OFF_ACBC = OFF_B2S + 1024;        // uint4[2][64]
constexpr int OFF_E    = OFF_ACBC + 2048;       // float[2][4]
constexpr int OFF_RED  = OFF_E + 32;            // [2][128][9][4] f32 = 36864
constexpr int OFF_CBUF = OFF_RED + 36864;       // float[2][4][128]
constexpr int SMEM_REQ = OFF_CBUF + 4096;       // 187424 B
}

__device__ __half g_W2h[256 * 256];             // fp16 W2 [k][j]

__global__ void prep_w2h(const float* __restrict__ W2) {
    int i = (blockIdx.x * 256 + threadIdx.x) * 4;
    float4 v = *(const float4*)(W2 + i);
    ((__half2*)g_W2h)[i / 2]     = __floats2half2_rn(v.x, v.y);
    ((__half2*)g_W2h)[i / 2 + 1] = __floats2half2_rn(v.z, v.w);
}

__device__ __forceinline__ void ldsm_x4_t(uint32_t* r, uint32_t a) {
    asm volatile("ldmatrix.sync.aligned.m8n8.x4.trans.shared.b16 {%0,%1,%2,%3}, [%4];"
                 : "=r"(r[0]), "=r"(r[1]), "=r"(r[2]), "=r"(r[3]) : "r"(a));
}
__device__ __forceinline__ void mma16816(float* c, const uint32_t* a,
                                         const uint32_t* b) {
    asm volatile(
        "mma.sync.aligned.m16n8k16.row.col.f32.f16.f16.f32 "
        "{%0,%1,%2,%3}, {%4,%5,%6,%7}, {%8,%9}, {%0,%1,%2,%3};"
        : "+f"(c[0]), "+f"(c[1]), "+f"(c[2]), "+f"(c[3])
        : "r"(a[0]), "r"(a[1]), "r"(a[2]), "r"(a[3]), "r"(b[0]), "r"(b[1]));
}
__device__ __forceinline__ void barg(int id) {
    asm volatile("bar.sync %0, 256;" :: "r"(id) : "memory");
}

__global__ __launch_bounds__(512, 1)
void nerf_mma6_kernel(const float* __restrict__ cam,
                      const float* __restrict__ rayv,
                      const float* __restrict__ W1,
                      const float* __restrict__ b1,
                      const float* __restrict__ b2,
                      const float* __restrict__ Wsig,
                      const float* __restrict__ bsig,
                      const float* __restrict__ Wrgb,
                      const float* __restrict__ brgb,
                      float* __restrict__ out,
                      int nrays)
{
    extern __shared__ char smem[];
    uint32_t smb;
    asm("{ .reg .u64 t; cvta.to.shared.u64 t, %1; cvt.u32.u64 %0, t; }"
        : "=r"(smb) : "l"(smem));

    const int tid = threadIdx.x;

    // ---- one-time staging (all 512 threads) ----
    {
        const uint4* src = (const uint4*)g_W2h;
        #pragma unroll
        for (int it = 0; it < 16; ++it) {
            int idx = tid + it * 512;
            int row = idx >> 5, c = idx & 31;
            *(uint4*)(smem + OFF_B + (row * AS + c * 8) * 2) = src[idx];
        }
    }
    if (tid < 256) {
        int k = tid;
        ((float4*)(smem + OFF_W1T))[k] =
            make_float4(W1[k], W1[256 + k], W1[512 + k], b1[k]);
        ((float4*)(smem + OFF_HDW))[k] =
            make_float4(Wsig[k], Wrgb[k*3+0], Wrgb[k*3+1], Wrgb[k*3+2]);
        ((float*)(smem + OFF_B2S))[k] = b2[k];
    }
    __syncthreads();

    // ---- group decomposition: g owns its own ray stream ----
    const int g = tid >> 8, gtid = tid & 255;
    const int wg = gtid >> 5, lane = gtid & 31;
    const int wm = wg & 3, wn_ = wg >> 2;
    const int q = lane & 3, rowq = lane >> 2;
    const int krow = lane & 15, bcol = (lane >> 4) * 8;
    const int barid = g + 1;

    __half2 zz[4];
    #pragma unroll
    for (int i = 0; i < 4; ++i) {
        int m = wm * 32 + (i >> 1) * 16 + rowq + (i & 1) * 8;   // p = m, 0..127
        float t = (float)m * (1.0f / 127.0f);
        zz[i] = __float2half2_rn(NEARV * (1.0f - t) + FARV * t);
    }
    const __half2 h2zero = __float2half2_rn(0.0f);
    const uint4* actab = (const uint4*)(smem + OFF_ACBC) + g * 64 + q;
    const float* b2s = (const float*)(smem + OFF_B2S);
    const float4* hdw = (const float4*)(smem + OFF_HDW);
    const float4* w1t = (const float4*)(smem + OFF_W1T);
    float* red = (float*)(smem + OFF_RED) + g * 4608;           // 128*9*4
    float* cbuf = (float*)(smem + OFF_CBUF) + g * 512;
    float* eg = (float*)(smem + OFF_E) + g * 4;
    const int slot = wn_ * 4 + q;

    for (int ray = blockIdx.x * 2 + g; ray < nrays; ray += 296) {
        // ---- per-ray prologue: A-gen table from SMEM W1 table ----
        if (gtid < 67) {
            float v0 = rayv[ray*3+0], v1 = rayv[ray*3+1], v2 = rayv[ray*3+2];
            float inv = rsqrtf(v0*v0 + v1*v1 + v2*v2);
            float dxr = v0*inv, dyr = v1*inv, dzr = v2*inv;
            if (gtid < 64) {
                int ks = gtid >> 2, qq = gtid & 3;
                int k0 = ks * 16 + qq * 2;
                float cc0 = cam[ray*3+0], cc1 = cam[ray*3+1], cc2 = cam[ray*3+2];
                float acf[4], bcf[4];
                #pragma unroll
                for (int u = 0; u < 4; ++u) {
                    int k = k0 + (u >> 1) * 8 + (u & 1);
                    float4 wv = w1t[k];
                    acf[u] = cc0*wv.x + cc1*wv.y + cc2*wv.z + wv.w;
                    bcf[u] = dxr*wv.x + dyr*wv.y + dzr*wv.z;
                }
                __half2 ac01 = __floats2half2_rn(acf[0], acf[1]);
                __half2 bc01 = __floats2half2_rn(bcf[0], bcf[1]);
                __half2 ac89 = __floats2half2_rn(acf[2], acf[3]);
                __half2 bc89 = __floats2half2_rn(bcf[2], bcf[3]);
                uint4 e;
                e.x = *(uint32_t*)&ac01; e.y = *(uint32_t*)&bc01;
                e.z = *(uint32_t*)&ac89; e.w = *(uint32_t*)&bc89;
                ((uint4*)(smem + OFF_ACBC))[g * 64 + gtid] = e;
            } else {
                int t = gtid - 64;     // 0..2
                eg[t] = brgb[t] - (dxr * Wrgb[(256+0)*3 + t] +
                                   dyr * Wrgb[(256+1)*3 + t] +
                                   dzr * Wrgb[(256+2)*3 + t]);
            }
        }
        barg(barid);

        // ---- mainloop: M=128 (this ray), N=256 in two passes ----
        float s[4][4];
        #pragma unroll
        for (int i = 0; i < 4; ++i)
            #pragma unroll
            for (int h = 0; h < 4; ++h) s[i][h] = 0.0f;

        #pragma unroll 1
        for (int pp = 0; pp < 2; ++pp) {
            const int n0 = pp * 128 + wn_ * 64;
            uint32_t baddr[4];
            #pragma unroll
            for (int nf2 = 0; nf2 < 4; ++nf2)
                baddr[nf2] = smb + OFF_B + (krow * AS + n0 + nf2 * 16 + bcol) * 2;

            float acc[2][8][4];
            #pragma unroll
            for (int mf = 0; mf < 2; ++mf)
                #pragma unroll
                for (int nf = 0; nf < 8; ++nf)
                    #pragma unroll
                    for (int c = 0; c < 4; ++c) acc[mf][nf][c] = 0.0f;

            #pragma unroll
            for (int ks = 0; ks < 16; ++ks) {
                uint4 e = actab[ks * 4];
                __half2 ac01 = *(__half2*)&e.x, bc01 = *(__half2*)&e.y;
                __half2 ac89 = *(__half2*)&e.z, bc89 = *(__half2*)&e.w;
                uint32_t a[2][4];
                #pragma unroll
                for (int mf = 0; mf < 2; ++mf) {
                    __half2 h0 = __hmax2(__hfma2(bc01, zz[mf*2],   ac01), h2zero);
                    __half2 h1 = __hmax2(__hfma2(bc01, zz[mf*2+1], ac01), h2zero);
                    __half2 h2 = __hmax2(__hfma2(bc89, zz[mf*2],   ac89), h2zero);
                    __half2 h3 = __hmax2(__hfma2(bc89, zz[mf*2+1], ac89), h2zero);
                    a[mf][0] = *(uint32_t*)&h0;
                    a[mf][1] = *(uint32_t*)&h1;
                    a[mf][2] = *(uint32_t*)&h2;
                    a[mf][3] = *(uint32_t*)&h3;
                }
                #pragma unroll
                for (int nf2 = 0; nf2 < 4; ++nf2) {
                    uint32_t b[4];
                    ldsm_x4_t(b, baddr[nf2] + ks * (16 * AS * 2));
                    #pragma unroll
                    for (int mf = 0; mf < 2; ++mf) {
                        mma16816(acc[mf][nf2*2],     a[mf], b);
                        mma16816(acc[mf][nf2*2 + 1], a[mf], b + 2);
                    }
                }
            }

            #pragma unroll
            for (int nf = 0; nf < 8; ++nf) {
                int j0 = n0 + nf * 8 + q * 2;
                float bb0 = b2s[j0], bb1 = b2s[j0 + 1];
                float4 w0v = hdw[j0], w1v = hdw[j0 + 1];
                #pragma unroll
                for (int mf = 0; mf < 2; ++mf) {
                    float h00 = fmaxf(acc[mf][nf][0] + bb0, 0.0f);
                    float h01 = fmaxf(acc[mf][nf][1] + bb1, 0.0f);
                    float h10 = fmaxf(acc[mf][nf][2] + bb0, 0.0f);
                    float h11 = fmaxf(acc[mf][nf][3] + bb1, 0.0f);
                    s[mf*2][0]   = fmaf(h00, w0v.x, fmaf(h01, w1v.x, s[mf*2][0]));
                    s[mf*2][1]   = fmaf(h00, w0v.y, fmaf(h01, w1v.y, s[mf*2][1]));
                    s[mf*2][2]   = fmaf(h00, w0v.z, fmaf(h01, w1v.z, s[mf*2][2]));
                    s[mf*2][3]   = fmaf(h00, w0v.w, fmaf(h01, w1v.w, s[mf*2][3]));
                    s[mf*2+1][0] = fmaf(h10, w0v.x, fmaf(h11, w1v.x, s[mf*2+1][0]));
                    s[mf*2+1][1] = fmaf(h10, w0v.y, fmaf(h11, w1v.y, s[mf*2+1][1]));
                    s[mf*2+1][2] = fmaf(h10, w0v.z, fmaf(h11, w1v.z, s[mf*2+1][2]));
                    s[mf*2+1][3] = fmaf(h10, w0v.w, fmaf(h11, w1v.w, s[mf*2+1][3]));
                }
            }
        }

        // ---- slot write + reduce (group-local) ----
        #pragma unroll
        for (int i = 0; i < 4; ++i) {
            int m = wm * 32 + (i >> 1) * 16 + rowq + (i & 1) * 8;
            *(float4*)(red + (m * 9 + slot) * 4) =
                make_float4(s[i][0], s[i][1], s[i][2], s[i][3]);
        }
        barg(barid);

        if (gtid < 128) {
            int p = gtid;
            float4 t0 = *(float4*)(red + (p * 9 + 0) * 4);
            #pragma unroll
            for (int sl = 1; sl < 8; ++sl) {
                float4 t = *(float4*)(red + (p * 9 + sl) * 4);
                t0.x += t.x; t0.y += t.y; t0.z += t.z; t0.w += t.w;
            }
            float sigma = fmaxf(t0.x + bsig[0], 0.0f);
            float ta = (float)p * (1.0f / 127.0f);
            float z0 = NEARV * (1.0f - ta) + FARV * ta;
            float tb = (float)(p + 1) * (1.0f / 127.0f);
            float z1 = NEARV * (1.0f - tb) + FARV * tb;
            float alpha = (p < 127) ? (1.0f - expf(-sigma * (z1 - z0))) : 1.0f;
            cbuf[p]       = alpha;
            cbuf[128 + p] = 1.0f / (1.0f + expf(-(t0.y + eg[0])));
            cbuf[256 + p] = 1.0f / (1.0f + expf(-(t0.z + eg[1])));
            cbuf[384 + p] = 1.0f / (1.0f + expf(-(t0.w + eg[2])));
        }
        barg(barid);

        // ---- warp-parallel composite (warp 0 of group) ----
        if (wg == 0) {
            int s0i = lane * 4;
            float a0 = cbuf[s0i], a1 = cbuf[s0i+1], a2 = cbuf[s0i+2], a3 = cbuf[s0i+3];
            float f0 = 1.0f - a0 + EPSV, f1 = 1.0f - a1 + EPSV;
            float f2 = 1.0f - a2 + EPSV, f3 = 1.0f - a3 + EPSV;
            float I = f0 * f1 * f2 * f3;
            #pragma unroll
            for (int d = 1; d < 32; d <<= 1) {
                float t = __shfl_up_sync(0xffffffffu, I, d);
                if (lane >= d) I *= t;
            }
            float E = __shfl_up_sync(0xffffffffu, I, 1);
            if (lane == 0) E = 1.0f;
            float T1 = E * f0, T2 = T1 * f1, T3 = T2 * f2;
            float w0 = a0 * E, w1 = a1 * T1, w2 = a2 * T2, w3 = a3 * T3;
            float o[3];
            #pragma unroll
            for (int ch = 0; ch < 3; ++ch) {
                const float* cc = cbuf + 128 * (ch + 1) + s0i;
                o[ch] = fmaf(w0, cc[0], fmaf(w1, cc[1],
                        fmaf(w2, cc[2], w3 * cc[3])));
                #pragma unroll
                for (int d = 16; d; d >>= 1)
                    o[ch] += __shfl_xor_sync(0xffffffffu, o[ch], d);
            }
            if (lane == 0) {
                out[ray*3 + 0] = o[0];
                out[ray*3 + 1] = o[1];
                out[ray*3 + 2] = o[2];
            }
        }
    }
}

extern "C" void kernel_launch(void* const* d_in, const int* in_sizes, int n_in,
                              void* d_out, int out_size)
{
    const float* cam  = (const float*)d_in[0];
    const float* rayv = (const float*)d_in[1];
    const float* W1   = (const float*)d_in[2];
    const float* b1   = (const float*)d_in[3];
    const float* W2   = (const float*)d_in[4];
    const float* b2   = (const float*)d_in[5];
    const float* Wsig = (const float*)d_in[6];
    const float* bsig = (const float*)d_in[7];
    const float* Wrgb = (const float*)d_in[8];
    const float* brgb = (const float*)d_in[9];
    float* out = (float*)d_out;

    const int nrays = in_sizes[0] / 3;     // 4096

    prep_w2h<<<64, 256>>>(W2);

    cudaFuncSetAttribute(nerf_mma6_kernel,
                         cudaFuncAttributeMaxDynamicSharedMemorySize, SMEM_REQ);
    nerf_mma6_kernel<<<148, 512, SMEM_REQ>>>(cam, rayv, W1, b1, b2,
                                             Wsig, bsig, Wrgb, brgb, out, nrays);
}